// round 13
// baseline (speedup 1.0000x reference)
#include <cuda_runtime.h>
#include <cuda_bf16.h>
#include <math.h>
#include <stdint.h>

// ---------------------------------------------------------------------------
// KAN layer as one concatenated GEMM (mma.sync bf16).
// K layout (KTOT=7168): [0,512) silu_hi*w_hi, [512,1024) silu_lo*w_hi,
// [1024,1536) silu_hi*w_lo, [1536,7168): k=1536+kk*512+i spline*(w*c)
// THIS ROUND: occupancy-2 experiment. BK=64, 96KB smem, 2 CTAs/SM,
// SPLITK=8 (256 CTAs over 148 SMs) -> 4 warps/SMSP to hide HMMA/LDS latency.
// ---------------------------------------------------------------------------

#define BATCH 1024
#define NIN   512
#define NOUT  512
#define NB    11
#define KSIL  1536
#define KTOT  7168

#define BM 128
#define BN 128
#define BK 64
#define SPLITK 8
#define KSPLIT (KTOT / SPLITK)     // 896
#define ITERS  (KSPLIT / BK)       // 14
#define STAGES 3
#define ASTAGE (BM * BK * 2)       // 16384
#define BSTAGE (BN * BK * 2)       // 16384
#define STAGE_BYTES (ASTAGE + BSTAGE)       // 32768
#define SMEM_TOTAL (STAGES * STAGE_BYTES)   // 98304 -> 2 CTAs/SM

// Scratch (allocation-free rule: __device__ globals)
__device__ __align__(128) __nv_bfloat16 g_A [(size_t)BATCH * KTOT];
__device__ __align__(128) __nv_bfloat16 g_Bt[(size_t)NOUT  * KTOT];
__device__ __align__(128) float         g_P [(size_t)SPLITK * BATCH * NOUT]; // 16MB

// ---------------------------------------------------------------------------
// prep_a: silu hi/lo + closed-form uniform cubic B-spline via smem scatter.
// knots t_m = -5.25 + 0.75*m; cell jc = floor((x+5.25)/0.75), u = frac.
// ---------------------------------------------------------------------------
__global__ void __launch_bounds__(256) prep_a_kernel(const float* __restrict__ X) {
    __shared__ uint32_t sc[256 * NB];          // per-thread 11-word scratch row
    const int tid = threadIdx.x;
    int pid = blockIdx.x * 256 + tid;
    int b  = pid >> 8;
    int ip = (pid & 255) << 1;
    float2 xv = *(const float2*)(X + (size_t)b * NIN + ip);

    float s0 = xv.x / (1.0f + __expf(-xv.x));
    float s1 = xv.y / (1.0f + __expf(-xv.y));
    __nv_bfloat16 shi0 = __float2bfloat16(s0), shi1 = __float2bfloat16(s1);
    __nv_bfloat16 slo0 = __float2bfloat16(s0 - __bfloat162float(shi0));
    __nv_bfloat16 slo1 = __float2bfloat16(s1 - __bfloat162float(shi1));

    __nv_bfloat16* row = g_A + (size_t)b * KTOT;
    *(__nv_bfloat162*)(row + ip)        = __nv_bfloat162(shi0, shi1);
    *(__nv_bfloat162*)(row + 512 + ip)  = __nv_bfloat162(slo0, slo1);
    *(__nv_bfloat162*)(row + 1024 + ip) = __nv_bfloat162(shi0, shi1);

#pragma unroll
    for (int kk = 0; kk < NB; kk++) sc[tid * NB + kk] = 0;

    unsigned short* sh = (unsigned short*)sc;
#pragma unroll
    for (int j = 0; j < 2; j++) {
        float x = j ? xv.y : xv.x;
        float pos = (x + 5.25f) * (1.0f / 0.75f);
        int jc = (int)floorf(pos);
        if (jc >= 0 && jc <= 13) {
            float u  = pos - (float)jc;
            float u2 = u * u, u3 = u2 * u;
            float omu = 1.0f - u;
            float w0 = omu * omu * omu * (1.0f / 6.0f);
            float w1 = (3.0f * u3 - 6.0f * u2 + 4.0f) * (1.0f / 6.0f);
            float w2 = (-3.0f * u3 + 3.0f * u2 + 3.0f * u + 1.0f) * (1.0f / 6.0f);
            float w3 = u3 * (1.0f / 6.0f);
#pragma unroll
            for (int d = 0; d < 4; d++) {
                int m = jc - 3 + d;
                if (m >= 0 && m <= 10) {
                    float wd = (d == 0) ? w0 : (d == 1) ? w1 : (d == 2) ? w2 : w3;
                    __nv_bfloat16 h = __float2bfloat16(wd);
                    sh[(tid * NB + m) * 2 + j] = *reinterpret_cast<unsigned short*>(&h);
                }
            }
        }
    }
#pragma unroll
    for (int kk = 0; kk < NB; kk++)
        *(uint32_t*)(row + KSIL + kk * NIN + ip) = sc[tid * NB + kk];
}

__global__ void __launch_bounds__(256) prep_b_kernel(const float* __restrict__ W,
                                                     const float* __restrict__ C) {
    int pid = blockIdx.x * 256 + threadIdx.x;
    int o  = pid >> 8;
    int ip = (pid & 255) << 1;

    float w0 = W[(size_t)ip * NOUT + o];
    float w1 = W[(size_t)(ip + 1) * NOUT + o];
    __nv_bfloat16 whi0 = __float2bfloat16(w0), whi1 = __float2bfloat16(w1);
    __nv_bfloat16 wlo0 = __float2bfloat16(w0 - __bfloat162float(whi0));
    __nv_bfloat16 wlo1 = __float2bfloat16(w1 - __bfloat162float(whi1));

    __nv_bfloat16* row = g_Bt + (size_t)o * KTOT;
    *(__nv_bfloat162*)(row + ip)        = __nv_bfloat162(whi0, whi1);
    *(__nv_bfloat162*)(row + 512 + ip)  = __nv_bfloat162(whi0, whi1);
    *(__nv_bfloat162*)(row + 1024 + ip) = __nv_bfloat162(wlo0, wlo1);

    const float* c0 = C + ((size_t)ip * NOUT + o) * NB;
    const float* c1 = C + ((size_t)(ip + 1) * NOUT + o) * NB;
#pragma unroll
    for (int kk = 0; kk < NB; kk++)
        *(__nv_bfloat162*)(row + KSIL + kk * NIN + ip) =
            __nv_bfloat162(__float2bfloat16(w0 * c0[kk]),
                           __float2bfloat16(w1 * c1[kk]));
}

// ---------------------------------------------------------------------------
// GEMM helpers
// ---------------------------------------------------------------------------
__device__ __forceinline__ void cpa16(uint32_t dst, const void* src) {
    asm volatile("cp.async.cg.shared.global [%0], [%1], 16;\n" :: "r"(dst), "l"(src));
}

#define LDSM_X4(r, addr)                                                       \
    asm volatile("ldmatrix.sync.aligned.m8n8.x4.shared.b16 {%0,%1,%2,%3}, [%4];\n" \
                 : "=r"((r)[0]), "=r"((r)[1]), "=r"((r)[2]), "=r"((r)[3])      \
                 : "r"(addr))

#define MMA16816(d, a, b0, b1)                                                 \
    asm volatile("mma.sync.aligned.m16n8k16.row.col.f32.bf16.bf16.f32 "        \
                 "{%0,%1,%2,%3}, {%4,%5,%6,%7}, {%8,%9}, {%0,%1,%2,%3};\n"     \
                 : "+f"((d)[0]), "+f"((d)[1]), "+f"((d)[2]), "+f"((d)[3])      \
                 : "r"((a)[0]), "r"((a)[1]), "r"((a)[2]), "r"((a)[3]),         \
                   "r"(b0), "r"(b1))

// stage: A = 128 rows x 64 cols bf16 (128B swizzled rows), B same
__device__ __forceinline__ void load_stage(const char* Ag, const char* Bg, int kt,
                                           int tid, uint32_t smem_u32) {
    uint32_t base = smem_u32 + (kt % STAGES) * STAGE_BYTES;
    const char* Ak = Ag + (size_t)kt * (BK * 2);
#pragma unroll
    for (int it = 0; it < 4; it++) {            // 1024 chunks of 16B
        int t = tid + it * 256;
        int r = t >> 3, c = t & 7;
        uint32_t dst = base + r * 128 + ((c ^ (r & 7)) << 4);
        cpa16(dst, Ak + (size_t)r * (KTOT * 2) + (c << 4));
    }
    const char* Bk = Bg + (size_t)kt * (BK * 2);
#pragma unroll
    for (int it = 0; it < 4; it++) {
        int t = tid + it * 256;
        int r = t >> 3, c = t & 7;
        uint32_t dst = base + ASTAGE + r * 128 + ((c ^ (r & 7)) << 4);
        cpa16(dst, Bk + (size_t)r * (KTOT * 2) + (c << 4));
    }
    asm volatile("cp.async.commit_group;\n" ::);
}

__global__ void __launch_bounds__(256, 2) kan_gemm_kernel() {
    extern __shared__ __align__(1024) char smem[];
    const uint32_t smem_u32 = (uint32_t)__cvta_generic_to_shared(smem);
    const int tid  = threadIdx.x;
    const int m0   = blockIdx.x * BM;
    const int n0   = blockIdx.y * BN;
    const int z    = blockIdx.z;

    const char* Ag = (const char*)g_A  + ((size_t)m0 * KTOT + (size_t)z * KSPLIT) * 2;
    const char* Bg = (const char*)g_Bt + ((size_t)n0 * KTOT + (size_t)z * KSPLIT) * 2;

    const int lane = tid & 31;
    const int warp = tid >> 5;
    const int wm   = warp >> 1;   // 0..3 : 32-row band
    const int wn   = warp & 1;    // 0..1 : 64-col band
    const int lr   = lane & 15;
    const int hf   = lane >> 4;

    float acc[2][8][4];
#pragma unroll
    for (int mt = 0; mt < 2; mt++)
#pragma unroll
        for (int nt = 0; nt < 8; nt++)
#pragma unroll
            for (int e = 0; e < 4; e++) acc[mt][nt][e] = 0.0f;

    load_stage(Ag, Bg, 0, tid, smem_u32);
    load_stage(Ag, Bg, 1, tid, smem_u32);
    load_stage(Ag, Bg, 2, tid, smem_u32);

    for (int kt = 0; kt < ITERS; kt++) {
        asm volatile("cp.async.wait_group 2;\n" ::);   // own stage-kt copies done
        __syncthreads();                               // all threads' copies visible

        const uint32_t sbase = smem_u32 + (kt % STAGES) * STAGE_BYTES;

#pragma unroll
        for (int ks = 0; ks < 4; ks++) {               // 4 k16-steps per BK=64
            uint32_t af[2][4], bf[4][4];
#pragma unroll
            for (int mt = 0; mt < 2; mt++) {
                int r  = wm * 32 + mt * 16 + lr;
                int ch = (ks * 2 + hf) ^ (r & 7);
                LDSM_X4(af[mt], sbase + r * 128 + (ch << 4));
            }
#pragma unroll
            for (int p = 0; p < 4; p++) {
                int r  = wn * 64 + p * 16 + lr;
                int ch = (ks * 2 + hf) ^ (r & 7);
                LDSM_X4(bf[p], sbase + ASTAGE + r * 128 + (ch << 4));
            }
#pragma unroll
            for (int mt = 0; mt < 2; mt++)
#pragma unroll
                for (int p = 0; p < 4; p++)
#pragma unroll
                    for (int q = 0; q < 2; q++)
                        MMA16816(acc[mt][p * 2 + q], af[mt], bf[p][q], bf[p][q + 2]);
        }
        __syncthreads();                               // readers done with slot kt%3

        if (kt + STAGES < ITERS)
            load_stage(Ag, Bg, kt + STAGES, tid, smem_u32);
        else
            asm volatile("cp.async.commit_group;\n" ::);
    }

    // epilogue: split-K partials
    float* P = g_P + (size_t)z * BATCH * NOUT;
#pragma unroll
    for (int mt = 0; mt < 2; mt++)
#pragma unroll
        for (int nt = 0; nt < 8; nt++) {
            int row0 = m0 + wm * 32 + mt * 16 + (lane >> 2);
            int col  = n0 + wn * 64 + nt * 8 + (lane & 3) * 2;
            *(float2*)&P[(size_t)row0 * NOUT + col] =
                make_float2(acc[mt][nt][0], acc[mt][nt][1]);
            *(float2*)&P[(size_t)(row0 + 8) * NOUT + col] =
                make_float2(acc[mt][nt][2], acc[mt][nt][3]);
        }
}

// ---------------------------------------------------------------------------
// Deterministic fixed-order split-K reduction (measured-good 512-CTA shape)
// ---------------------------------------------------------------------------
__global__ void __launch_bounds__(256) reduce_kernel(float* __restrict__ Out) {
    int idx = blockIdx.x * 256 + threadIdx.x;           // over float4s
    const size_t Q = (size_t)BATCH * NOUT / 4;
    const float4* P = (const float4*)g_P;
    float4 v[8];
#pragma unroll
    for (int z = 0; z < 8; z++) v[z] = P[(size_t)z * Q + idx];
    float4 r;
    r.x = ((v[0].x + v[1].x) + (v[2].x + v[3].x)) + ((v[4].x + v[5].x) + (v[6].x + v[7].x));
    r.y = ((v[0].y + v[1].y) + (v[2].y + v[3].y)) + ((v[4].y + v[5].y) + (v[6].y + v[7].y));
    r.z = ((v[0].z + v[1].z) + (v[2].z + v[3].z)) + ((v[4].z + v[5].z) + (v[6].z + v[7].z));
    r.w = ((v[0].w + v[1].w) + (v[2].w + v[3].w)) + ((v[4].w + v[5].w) + (v[6].w + v[7].w));
    ((float4*)Out)[idx] = r;
}

// ---------------------------------------------------------------------------
extern "C" void kernel_launch(void* const* d_in, const int* in_sizes, int n_in,
                              void* d_out, int out_size) {
    const float* X = nullptr;
    const float* C = nullptr;
    const float* W = nullptr;
    for (int i = 0; i < n_in; i++) {
        if      (in_sizes[i] == BATCH * NIN)      X = (const float*)d_in[i];
        else if (in_sizes[i] == NIN * NOUT * NB)  C = (const float*)d_in[i];
        else if (in_sizes[i] == NIN * NOUT)       W = (const float*)d_in[i];
    }

    static bool attr_done = false;
    if (!attr_done) {
        cudaFuncSetAttribute(kan_gemm_kernel,
                             cudaFuncAttributeMaxDynamicSharedMemorySize, SMEM_TOTAL);
        attr_done = true;
    }

    prep_a_kernel<<<(BATCH * NIN / 2) / 256, 256>>>(X);
    prep_b_kernel<<<(NIN * NOUT / 2) / 256, 256>>>(W, C);

    dim3 grid(BATCH / BM, NOUT / BN, SPLITK);   // (8, 4, 8) = 256 CTAs, occ 2
    kan_gemm_kernel<<<grid, 256, SMEM_TOTAL>>>();

    reduce_kernel<<<(BATCH * NOUT / 4) / 256, 256>>>((float*)d_out);
}

// round 14
// speedup vs baseline: 1.5603x; 1.5603x over previous
#include <cuda_runtime.h>
#include <cuda_bf16.h>
#include <math.h>
#include <stdint.h>

// ---------------------------------------------------------------------------
// KAN layer as one concatenated GEMM (mma.sync bf16 — measured-best path).
// K layout (KTOT=7168): [0,512) silu_hi*w_hi, [512,1024) silu_lo*w_hi,
// [1024,1536) silu_hi*w_lo, [1536,7168): k=1536+kk*512+i spline*(w*c)
// GEMM/preps = round-11 measured-best (49.66us total) verbatim.
// Reduce: 2x TLP (1024 CTAs x 256 thr, float2/thread), same fixed order.
// ---------------------------------------------------------------------------

#define BATCH 1024
#define NIN   512
#define NOUT  512
#define NB    11
#define KSIL  1536
#define KTOT  7168

#define BM 128
#define BN 128
#define BK 128
#define SPLITK 4
#define KSPLIT (KTOT / SPLITK)     // 1792
#define ITERS  (KSPLIT / BK)       // 14
#define STAGES 3
#define ASTAGE (BM * BK * 2)       // 32768
#define BSTAGE (BN * BK * 2)       // 32768
#define STAGE_BYTES (ASTAGE + BSTAGE)
#define SMEM_TOTAL (STAGES * STAGE_BYTES)   // 196608
#define SUBTILE 16384              // 128 rows x 64 cols bf16 (SW128 atom tile)

// Scratch (allocation-free rule: __device__ globals)
__device__ __align__(128) __nv_bfloat16 g_A [(size_t)BATCH * KTOT];
__device__ __align__(128) __nv_bfloat16 g_Bt[(size_t)NOUT  * KTOT];
__device__ __align__(128) float         g_P [(size_t)SPLITK * BATCH * NOUT];

// ---------------------------------------------------------------------------
// prep_a: silu hi/lo + closed-form uniform cubic B-spline via smem scatter.
// knots t_m = -5.25 + 0.75*m; cell jc = floor((x+5.25)/0.75), u = frac.
// ---------------------------------------------------------------------------
__global__ void __launch_bounds__(256) prep_a_kernel(const float* __restrict__ X) {
    __shared__ uint32_t sc[256 * NB];          // per-thread 11-word scratch row
    const int tid = threadIdx.x;
    int pid = blockIdx.x * 256 + tid;
    int b  = pid >> 8;
    int ip = (pid & 255) << 1;
    float2 xv = *(const float2*)(X + (size_t)b * NIN + ip);

    float s0 = xv.x / (1.0f + __expf(-xv.x));
    float s1 = xv.y / (1.0f + __expf(-xv.y));
    __nv_bfloat16 shi0 = __float2bfloat16(s0), shi1 = __float2bfloat16(s1);
    __nv_bfloat16 slo0 = __float2bfloat16(s0 - __bfloat162float(shi0));
    __nv_bfloat16 slo1 = __float2bfloat16(s1 - __bfloat162float(shi1));

    __nv_bfloat16* row = g_A + (size_t)b * KTOT;
    *(__nv_bfloat162*)(row + ip)        = __nv_bfloat162(shi0, shi1);
    *(__nv_bfloat162*)(row + 512 + ip)  = __nv_bfloat162(slo0, slo1);
    *(__nv_bfloat162*)(row + 1024 + ip) = __nv_bfloat162(shi0, shi1);

    // zero this thread's scratch row (stride-11 words -> conflict-free)
#pragma unroll
    for (int kk = 0; kk < NB; kk++) sc[tid * NB + kk] = 0;

    unsigned short* sh = (unsigned short*)sc;
#pragma unroll
    for (int j = 0; j < 2; j++) {
        float x = j ? xv.y : xv.x;
        float pos = (x + 5.25f) * (1.0f / 0.75f);
        int jc = (int)floorf(pos);
        if (jc >= 0 && jc <= 13) {
            float u  = pos - (float)jc;
            float u2 = u * u, u3 = u2 * u;
            float omu = 1.0f - u;
            float w0 = omu * omu * omu * (1.0f / 6.0f);
            float w1 = (3.0f * u3 - 6.0f * u2 + 4.0f) * (1.0f / 6.0f);
            float w2 = (-3.0f * u3 + 3.0f * u2 + 3.0f * u + 1.0f) * (1.0f / 6.0f);
            float w3 = u3 * (1.0f / 6.0f);
#pragma unroll
            for (int d = 0; d < 4; d++) {
                int m = jc - 3 + d;
                if (m >= 0 && m <= 10) {
                    float wd = (d == 0) ? w0 : (d == 1) ? w1 : (d == 2) ? w2 : w3;
                    __nv_bfloat16 h = __float2bfloat16(wd);
                    sh[(tid * NB + m) * 2 + j] = *reinterpret_cast<unsigned short*>(&h);
                }
            }
        }
    }
    // per-thread scratch: no sync needed; copy 11 words coalesced to global
#pragma unroll
    for (int kk = 0; kk < NB; kk++)
        *(uint32_t*)(row + KSIL + kk * NIN + ip) = sc[tid * NB + kk];
}

__global__ void __launch_bounds__(256) prep_b_kernel(const float* __restrict__ W,
                                                     const float* __restrict__ C) {
    int pid = blockIdx.x * 256 + threadIdx.x;
    int o  = pid >> 8;
    int ip = (pid & 255) << 1;

    float w0 = W[(size_t)ip * NOUT + o];
    float w1 = W[(size_t)(ip + 1) * NOUT + o];
    __nv_bfloat16 whi0 = __float2bfloat16(w0), whi1 = __float2bfloat16(w1);
    __nv_bfloat16 wlo0 = __float2bfloat16(w0 - __bfloat162float(whi0));
    __nv_bfloat16 wlo1 = __float2bfloat16(w1 - __bfloat162float(whi1));

    __nv_bfloat16* row = g_Bt + (size_t)o * KTOT;
    *(__nv_bfloat162*)(row + ip)        = __nv_bfloat162(whi0, whi1);
    *(__nv_bfloat162*)(row + 512 + ip)  = __nv_bfloat162(whi0, whi1);
    *(__nv_bfloat162*)(row + 1024 + ip) = __nv_bfloat162(wlo0, wlo1);

    const float* c0 = C + ((size_t)ip * NOUT + o) * NB;
    const float* c1 = C + ((size_t)(ip + 1) * NOUT + o) * NB;
#pragma unroll
    for (int kk = 0; kk < NB; kk++)
        *(__nv_bfloat162*)(row + KSIL + kk * NIN + ip) =
            __nv_bfloat162(__float2bfloat16(w0 * c0[kk]),
                           __float2bfloat16(w1 * c1[kk]));
}

// ---------------------------------------------------------------------------
// GEMM helpers (measured-36us kernel, verbatim)
// ---------------------------------------------------------------------------
__device__ __forceinline__ void cpa16(uint32_t dst, const void* src) {
    asm volatile("cp.async.cg.shared.global [%0], [%1], 16;\n" :: "r"(dst), "l"(src));
}

#define LDSM_X4(r, addr)                                                       \
    asm volatile("ldmatrix.sync.aligned.m8n8.x4.shared.b16 {%0,%1,%2,%3}, [%4];\n" \
                 : "=r"((r)[0]), "=r"((r)[1]), "=r"((r)[2]), "=r"((r)[3])      \
                 : "r"(addr))

#define MMA16816(d, a, b0, b1)                                                 \
    asm volatile("mma.sync.aligned.m16n8k16.row.col.f32.bf16.bf16.f32 "        \
                 "{%0,%1,%2,%3}, {%4,%5,%6,%7}, {%8,%9}, {%0,%1,%2,%3};\n"     \
                 : "+f"((d)[0]), "+f"((d)[1]), "+f"((d)[2]), "+f"((d)[3])      \
                 : "r"((a)[0]), "r"((a)[1]), "r"((a)[2]), "r"((a)[3]),         \
                   "r"(b0), "r"(b1))

__device__ __forceinline__ void load_stage(const char* Ag, const char* Bg, int kt,
                                           int tid, uint32_t smem_u32) {
    uint32_t base = smem_u32 + (kt % STAGES) * STAGE_BYTES;
    const char* Ak = Ag + (size_t)kt * (BK * 2);
#pragma unroll
    for (int it = 0; it < 8; it++) {
        int t = tid + it * 256;
        int r = t >> 4, c = t & 15;
        uint32_t dst = base + ((c >> 3) << 14) + r * 128 + (((c & 7) ^ (r & 7)) << 4);
        cpa16(dst, Ak + (size_t)r * (KTOT * 2) + (c << 4));
    }
    const char* Bk = Bg + (size_t)kt * (BK * 2);
#pragma unroll
    for (int it = 0; it < 8; it++) {
        int t = tid + it * 256;
        int r = t >> 4, c = t & 15;
        uint32_t dst = base + ASTAGE + ((c >> 3) << 14) + r * 128 + (((c & 7) ^ (r & 7)) << 4);
        cpa16(dst, Bk + (size_t)r * (KTOT * 2) + (c << 4));
    }
    asm volatile("cp.async.commit_group;\n" ::);
}

__global__ void __launch_bounds__(256, 1) kan_gemm_kernel() {
    extern __shared__ __align__(1024) char smem[];
    const uint32_t smem_u32 = (uint32_t)__cvta_generic_to_shared(smem);
    const int tid  = threadIdx.x;
    const int m0   = blockIdx.x * BM;
    const int n0   = blockIdx.y * BN;
    const int z    = blockIdx.z;

    const char* Ag = (const char*)g_A  + ((size_t)m0 * KTOT + (size_t)z * KSPLIT) * 2;
    const char* Bg = (const char*)g_Bt + ((size_t)n0 * KTOT + (size_t)z * KSPLIT) * 2;

    const int lane = tid & 31;
    const int warp = tid >> 5;
    const int wm   = warp >> 1;   // 0..3 : 32-row band
    const int wn   = warp & 1;    // 0..1 : 64-col band
    const int lr   = lane & 15;
    const int hf   = lane >> 4;

    float acc[2][8][4];
#pragma unroll
    for (int mt = 0; mt < 2; mt++)
#pragma unroll
        for (int nt = 0; nt < 8; nt++)
#pragma unroll
            for (int e = 0; e < 4; e++) acc[mt][nt][e] = 0.0f;

    load_stage(Ag, Bg, 0, tid, smem_u32);
    load_stage(Ag, Bg, 1, tid, smem_u32);
    load_stage(Ag, Bg, 2, tid, smem_u32);

    for (int kt = 0; kt < ITERS; kt++) {
        asm volatile("cp.async.wait_group 2;\n" ::);
        __syncthreads();

        const uint32_t sbase = smem_u32 + (kt % STAGES) * STAGE_BYTES;

#pragma unroll
        for (int ks = 0; ks < 8; ks++) {
            const int sub = ks >> 2;
            const int ck  = ks & 3;
            uint32_t af[2][4], bf[4][4];
#pragma unroll
            for (int mt = 0; mt < 2; mt++) {
                int r  = wm * 32 + mt * 16 + lr;
                int ch = (ck * 2 + hf) ^ (r & 7);
                LDSM_X4(af[mt], sbase + sub * SUBTILE + r * 128 + (ch << 4));
            }
#pragma unroll
            for (int p = 0; p < 4; p++) {
                int r  = wn * 64 + p * 16 + lr;
                int ch = (ck * 2 + hf) ^ (r & 7);
                LDSM_X4(bf[p], sbase + ASTAGE + sub * SUBTILE + r * 128 + (ch << 4));
            }
#pragma unroll
            for (int mt = 0; mt < 2; mt++)
#pragma unroll
                for (int p = 0; p < 4; p++)
#pragma unroll
                    for (int q = 0; q < 2; q++)
                        MMA16816(acc[mt][p * 2 + q], af[mt], bf[p][q], bf[p][q + 2]);
        }
        __syncthreads();

        if (kt + STAGES < ITERS)
            load_stage(Ag, Bg, kt + STAGES, tid, smem_u32);
        else
            asm volatile("cp.async.commit_group;\n" ::);
    }

    // epilogue: split-K partials
    float* P = g_P + (size_t)z * BATCH * NOUT;
#pragma unroll
    for (int mt = 0; mt < 2; mt++)
#pragma unroll
        for (int nt = 0; nt < 8; nt++) {
            int row0 = m0 + wm * 32 + mt * 16 + (lane >> 2);
            int col  = n0 + wn * 64 + nt * 8 + (lane & 3) * 2;
            *(float2*)&P[(size_t)row0 * NOUT + col] =
                make_float2(acc[mt][nt][0], acc[mt][nt][1]);
            *(float2*)&P[(size_t)(row0 + 8) * NOUT + col] =
                make_float2(acc[mt][nt][2], acc[mt][nt][3]);
        }
}

// ---------------------------------------------------------------------------
// Deterministic fixed-order split-K reduction — 2x TLP (float2 per thread)
// ---------------------------------------------------------------------------
__global__ void __launch_bounds__(256) reduce_kernel(float* __restrict__ Out) {
    int idx = blockIdx.x * 256 + threadIdx.x;           // over float2s (262144)
    const size_t Q = (size_t)BATCH * NOUT / 2;
    const float2* P = (const float2*)g_P;
    float2 a = P[0 * Q + idx];
    float2 b = P[1 * Q + idx];
    float2 c = P[2 * Q + idx];
    float2 d = P[3 * Q + idx];
    float2 r;
    r.x = (a.x + b.x) + (c.x + d.x);
    r.y = (a.y + b.y) + (c.y + d.y);
    ((float2*)Out)[idx] = r;
}

// ---------------------------------------------------------------------------
extern "C" void kernel_launch(void* const* d_in, const int* in_sizes, int n_in,
                              void* d_out, int out_size) {
    const float* X = nullptr;
    const float* C = nullptr;
    const float* W = nullptr;
    for (int i = 0; i < n_in; i++) {
        if      (in_sizes[i] == BATCH * NIN)      X = (const float*)d_in[i];
        else if (in_sizes[i] == NIN * NOUT * NB)  C = (const float*)d_in[i];
        else if (in_sizes[i] == NIN * NOUT)       W = (const float*)d_in[i];
    }

    static bool attr_done = false;
    if (!attr_done) {
        cudaFuncSetAttribute(kan_gemm_kernel,
                             cudaFuncAttributeMaxDynamicSharedMemorySize, SMEM_TOTAL);
        attr_done = true;
    }

    prep_a_kernel<<<(BATCH * NIN / 2) / 256, 256>>>(X);
    prep_b_kernel<<<(NIN * NOUT / 2) / 256, 256>>>(W, C);

    dim3 grid(BATCH / BM, NOUT / BN, SPLITK);   // (8, 4, 4) = 128 CTAs
    kan_gemm_kernel<<<grid, 256, SMEM_TOTAL>>>();

    reduce_kernel<<<(BATCH * NOUT / 2) / 256, 256>>>((float*)d_out);
}

// round 15
// speedup vs baseline: 1.5992x; 1.0250x over previous
#include <cuda_runtime.h>
#include <cuda_bf16.h>
#include <math.h>
#include <stdint.h>

// ---------------------------------------------------------------------------
// KAN layer as one concatenated GEMM (mma.sync bf16 — measured-best path).
// K layout (KTOT=7168): [0,512) silu_hi*w_hi, [512,1024) silu_lo*w_hi,
// [1024,1536) silu_hi*w_lo, [1536,7168): k=1536+kk*512+i spline*(w*c)
// GEMM/preps/reduce = measured-best forms. NEW: prep_a and prep_b run on
// forked streams inside the captured graph (they are fully independent),
// removing prep_b from the critical path.
// ---------------------------------------------------------------------------

#define BATCH 1024
#define NIN   512
#define NOUT  512
#define NB    11
#define KSIL  1536
#define KTOT  7168

#define BM 128
#define BN 128
#define BK 128
#define SPLITK 4
#define KSPLIT (KTOT / SPLITK)     // 1792
#define ITERS  (KSPLIT / BK)       // 14
#define STAGES 3
#define ASTAGE (BM * BK * 2)       // 32768
#define BSTAGE (BN * BK * 2)       // 32768
#define STAGE_BYTES (ASTAGE + BSTAGE)
#define SMEM_TOTAL (STAGES * STAGE_BYTES)   // 196608
#define SUBTILE 16384              // 128 rows x 64 cols bf16 (SW128 atom tile)

// Scratch (allocation-free rule: __device__ globals)
__device__ __align__(128) __nv_bfloat16 g_A [(size_t)BATCH * KTOT];
__device__ __align__(128) __nv_bfloat16 g_Bt[(size_t)NOUT  * KTOT];
__device__ __align__(128) float         g_P [(size_t)SPLITK * BATCH * NOUT];

// ---------------------------------------------------------------------------
// prep_a: silu hi/lo + closed-form uniform cubic B-spline via smem scatter.
// knots t_m = -5.25 + 0.75*m; cell jc = floor((x+5.25)/0.75), u = frac.
// ---------------------------------------------------------------------------
__global__ void __launch_bounds__(256) prep_a_kernel(const float* __restrict__ X) {
    __shared__ uint32_t sc[256 * NB];          // per-thread 11-word scratch row
    const int tid = threadIdx.x;
    int pid = blockIdx.x * 256 + tid;
    int b  = pid >> 8;
    int ip = (pid & 255) << 1;
    float2 xv = *(const float2*)(X + (size_t)b * NIN + ip);

    float s0 = xv.x / (1.0f + __expf(-xv.x));
    float s1 = xv.y / (1.0f + __expf(-xv.y));
    __nv_bfloat16 shi0 = __float2bfloat16(s0), shi1 = __float2bfloat16(s1);
    __nv_bfloat16 slo0 = __float2bfloat16(s0 - __bfloat162float(shi0));
    __nv_bfloat16 slo1 = __float2bfloat16(s1 - __bfloat162float(shi1));

    __nv_bfloat16* row = g_A + (size_t)b * KTOT;
    *(__nv_bfloat162*)(row + ip)        = __nv_bfloat162(shi0, shi1);
    *(__nv_bfloat162*)(row + 512 + ip)  = __nv_bfloat162(slo0, slo1);
    *(__nv_bfloat162*)(row + 1024 + ip) = __nv_bfloat162(shi0, shi1);

    // zero this thread's scratch row (stride-11 words -> conflict-free)
#pragma unroll
    for (int kk = 0; kk < NB; kk++) sc[tid * NB + kk] = 0;

    unsigned short* sh = (unsigned short*)sc;
#pragma unroll
    for (int j = 0; j < 2; j++) {
        float x = j ? xv.y : xv.x;
        float pos = (x + 5.25f) * (1.0f / 0.75f);
        int jc = (int)floorf(pos);
        if (jc >= 0 && jc <= 13) {
            float u  = pos - (float)jc;
            float u2 = u * u, u3 = u2 * u;
            float omu = 1.0f - u;
            float w0 = omu * omu * omu * (1.0f / 6.0f);
            float w1 = (3.0f * u3 - 6.0f * u2 + 4.0f) * (1.0f / 6.0f);
            float w2 = (-3.0f * u3 + 3.0f * u2 + 3.0f * u + 1.0f) * (1.0f / 6.0f);
            float w3 = u3 * (1.0f / 6.0f);
#pragma unroll
            for (int d = 0; d < 4; d++) {
                int m = jc - 3 + d;
                if (m >= 0 && m <= 10) {
                    float wd = (d == 0) ? w0 : (d == 1) ? w1 : (d == 2) ? w2 : w3;
                    __nv_bfloat16 h = __float2bfloat16(wd);
                    sh[(tid * NB + m) * 2 + j] = *reinterpret_cast<unsigned short*>(&h);
                }
            }
        }
    }
    // per-thread scratch: no sync needed; copy 11 words coalesced to global
#pragma unroll
    for (int kk = 0; kk < NB; kk++)
        *(uint32_t*)(row + KSIL + kk * NIN + ip) = sc[tid * NB + kk];
}

__global__ void __launch_bounds__(256) prep_b_kernel(const float* __restrict__ W,
                                                     const float* __restrict__ C) {
    int pid = blockIdx.x * 256 + threadIdx.x;
    int o  = pid >> 8;
    int ip = (pid & 255) << 1;

    float w0 = W[(size_t)ip * NOUT + o];
    float w1 = W[(size_t)(ip + 1) * NOUT + o];
    __nv_bfloat16 whi0 = __float2bfloat16(w0), whi1 = __float2bfloat16(w1);
    __nv_bfloat16 wlo0 = __float2bfloat16(w0 - __bfloat162float(whi0));
    __nv_bfloat16 wlo1 = __float2bfloat16(w1 - __bfloat162float(whi1));

    __nv_bfloat16* row = g_Bt + (size_t)o * KTOT;
    *(__nv_bfloat162*)(row + ip)        = __nv_bfloat162(whi0, whi1);
    *(__nv_bfloat162*)(row + 512 + ip)  = __nv_bfloat162(whi0, whi1);
    *(__nv_bfloat162*)(row + 1024 + ip) = __nv_bfloat162(wlo0, wlo1);

    const float* c0 = C + ((size_t)ip * NOUT + o) * NB;
    const float* c1 = C + ((size_t)(ip + 1) * NOUT + o) * NB;
#pragma unroll
    for (int kk = 0; kk < NB; kk++)
        *(__nv_bfloat162*)(row + KSIL + kk * NIN + ip) =
            __nv_bfloat162(__float2bfloat16(w0 * c0[kk]),
                           __float2bfloat16(w1 * c1[kk]));
}

// ---------------------------------------------------------------------------
// GEMM helpers (measured-36us kernel, verbatim)
// ---------------------------------------------------------------------------
__device__ __forceinline__ void cpa16(uint32_t dst, const void* src) {
    asm volatile("cp.async.cg.shared.global [%0], [%1], 16;\n" :: "r"(dst), "l"(src));
}

#define LDSM_X4(r, addr)                                                       \
    asm volatile("ldmatrix.sync.aligned.m8n8.x4.shared.b16 {%0,%1,%2,%3}, [%4];\n" \
                 : "=r"((r)[0]), "=r"((r)[1]), "=r"((r)[2]), "=r"((r)[3])      \
                 : "r"(addr))

#define MMA16816(d, a, b0, b1)                                                 \
    asm volatile("mma.sync.aligned.m16n8k16.row.col.f32.bf16.bf16.f32 "        \
                 "{%0,%1,%2,%3}, {%4,%5,%6,%7}, {%8,%9}, {%0,%1,%2,%3};\n"     \
                 : "+f"((d)[0]), "+f"((d)[1]), "+f"((d)[2]), "+f"((d)[3])      \
                 : "r"((a)[0]), "r"((a)[1]), "r"((a)[2]), "r"((a)[3]),         \
                   "r"(b0), "r"(b1))

__device__ __forceinline__ void load_stage(const char* Ag, const char* Bg, int kt,
                                           int tid, uint32_t smem_u32) {
    uint32_t base = smem_u32 + (kt % STAGES) * STAGE_BYTES;
    const char* Ak = Ag + (size_t)kt * (BK * 2);
#pragma unroll
    for (int it = 0; it < 8; it++) {
        int t = tid + it * 256;
        int r = t >> 4, c = t & 15;
        uint32_t dst = base + ((c >> 3) << 14) + r * 128 + (((c & 7) ^ (r & 7)) << 4);
        cpa16(dst, Ak + (size_t)r * (KTOT * 2) + (c << 4));
    }
    const char* Bk = Bg + (size_t)kt * (BK * 2);
#pragma unroll
    for (int it = 0; it < 8; it++) {
        int t = tid + it * 256;
        int r = t >> 4, c = t & 15;
        uint32_t dst = base + ASTAGE + ((c >> 3) << 14) + r * 128 + (((c & 7) ^ (r & 7)) << 4);
        cpa16(dst, Bk + (size_t)r * (KTOT * 2) + (c << 4));
    }
    asm volatile("cp.async.commit_group;\n" ::);
}

__global__ void __launch_bounds__(256, 1) kan_gemm_kernel() {
    extern __shared__ __align__(1024) char smem[];
    const uint32_t smem_u32 = (uint32_t)__cvta_generic_to_shared(smem);
    const int tid  = threadIdx.x;
    const int m0   = blockIdx.x * BM;
    const int n0   = blockIdx.y * BN;
    const int z    = blockIdx.z;

    const char* Ag = (const char*)g_A  + ((size_t)m0 * KTOT + (size_t)z * KSPLIT) * 2;
    const char* Bg = (const char*)g_Bt + ((size_t)n0 * KTOT + (size_t)z * KSPLIT) * 2;

    const int lane = tid & 31;
    const int warp = tid >> 5;
    const int wm   = warp >> 1;   // 0..3 : 32-row band
    const int wn   = warp & 1;    // 0..1 : 64-col band
    const int lr   = lane & 15;
    const int hf   = lane >> 4;

    float acc[2][8][4];
#pragma unroll
    for (int mt = 0; mt < 2; mt++)
#pragma unroll
        for (int nt = 0; nt < 8; nt++)
#pragma unroll
            for (int e = 0; e < 4; e++) acc[mt][nt][e] = 0.0f;

    load_stage(Ag, Bg, 0, tid, smem_u32);
    load_stage(Ag, Bg, 1, tid, smem_u32);
    load_stage(Ag, Bg, 2, tid, smem_u32);

    for (int kt = 0; kt < ITERS; kt++) {
        asm volatile("cp.async.wait_group 2;\n" ::);
        __syncthreads();

        const uint32_t sbase = smem_u32 + (kt % STAGES) * STAGE_BYTES;

#pragma unroll
        for (int ks = 0; ks < 8; ks++) {
            const int sub = ks >> 2;
            const int ck  = ks & 3;
            uint32_t af[2][4], bf[4][4];
#pragma unroll
            for (int mt = 0; mt < 2; mt++) {
                int r  = wm * 32 + mt * 16 + lr;
                int ch = (ck * 2 + hf) ^ (r & 7);
                LDSM_X4(af[mt], sbase + sub * SUBTILE + r * 128 + (ch << 4));
            }
#pragma unroll
            for (int p = 0; p < 4; p++) {
                int r  = wn * 64 + p * 16 + lr;
                int ch = (ck * 2 + hf) ^ (r & 7);
                LDSM_X4(bf[p], sbase + ASTAGE + sub * SUBTILE + r * 128 + (ch << 4));
            }
#pragma unroll
            for (int mt = 0; mt < 2; mt++)
#pragma unroll
                for (int p = 0; p < 4; p++)
#pragma unroll
                    for (int q = 0; q < 2; q++)
                        MMA16816(acc[mt][p * 2 + q], af[mt], bf[p][q], bf[p][q + 2]);
        }
        __syncthreads();

        if (kt + STAGES < ITERS)
            load_stage(Ag, Bg, kt + STAGES, tid, smem_u32);
        else
            asm volatile("cp.async.commit_group;\n" ::);
    }

    // epilogue: split-K partials
    float* P = g_P + (size_t)z * BATCH * NOUT;
#pragma unroll
    for (int mt = 0; mt < 2; mt++)
#pragma unroll
        for (int nt = 0; nt < 8; nt++) {
            int row0 = m0 + wm * 32 + mt * 16 + (lane >> 2);
            int col  = n0 + wn * 64 + nt * 8 + (lane & 3) * 2;
            *(float2*)&P[(size_t)row0 * NOUT + col] =
                make_float2(acc[mt][nt][0], acc[mt][nt][1]);
            *(float2*)&P[(size_t)(row0 + 8) * NOUT + col] =
                make_float2(acc[mt][nt][2], acc[mt][nt][3]);
        }
}

// ---------------------------------------------------------------------------
// Deterministic fixed-order split-K reduction (measured-good 512-CTA form)
// ---------------------------------------------------------------------------
__global__ void __launch_bounds__(256) reduce_kernel(float* __restrict__ Out) {
    int idx = blockIdx.x * 256 + threadIdx.x;           // over float4s
    const float4* P0 = (const float4*)(g_P + 0 * (size_t)BATCH * NOUT);
    const float4* P1 = (const float4*)(g_P + 1 * (size_t)BATCH * NOUT);
    const float4* P2 = (const float4*)(g_P + 2 * (size_t)BATCH * NOUT);
    const float4* P3 = (const float4*)(g_P + 3 * (size_t)BATCH * NOUT);
    float4 a = P0[idx], b = P1[idx], c = P2[idx], d = P3[idx];
    float4 r;
    r.x = (a.x + b.x) + (c.x + d.x);
    r.y = (a.y + b.y) + (c.y + d.y);
    r.z = (a.z + b.z) + (c.z + d.z);
    r.w = (a.w + b.w) + (c.w + d.w);
    ((float4*)Out)[idx] = r;
}

// ---------------------------------------------------------------------------
extern "C" void kernel_launch(void* const* d_in, const int* in_sizes, int n_in,
                              void* d_out, int out_size) {
    const float* X = nullptr;
    const float* C = nullptr;
    const float* W = nullptr;
    for (int i = 0; i < n_in; i++) {
        if      (in_sizes[i] == BATCH * NIN)      X = (const float*)d_in[i];
        else if (in_sizes[i] == NIN * NOUT * NB)  C = (const float*)d_in[i];
        else if (in_sizes[i] == NIN * NOUT)       W = (const float*)d_in[i];
    }

    // one-time host-side objects (no device memory; created outside capture
    // because the first call is the eager correctness run)
    static cudaStream_t s2 = nullptr;
    static cudaEvent_t ev_fork = nullptr, ev_join = nullptr;
    if (!s2) {
        cudaStreamCreateWithFlags(&s2, cudaStreamNonBlocking);
        cudaEventCreateWithFlags(&ev_fork, cudaEventDisableTiming);
        cudaEventCreateWithFlags(&ev_join, cudaEventDisableTiming);
        cudaFuncSetAttribute(kan_gemm_kernel,
                             cudaFuncAttributeMaxDynamicSharedMemorySize, SMEM_TOTAL);
    }

    // fork: prep_b on s2, prep_a on the main stream (independent kernels)
    cudaEventRecord(ev_fork, 0);
    cudaStreamWaitEvent(s2, ev_fork, 0);
    prep_b_kernel<<<(NIN * NOUT / 2) / 256, 256, 0, s2>>>(W, C);
    cudaEventRecord(ev_join, s2);

    prep_a_kernel<<<(BATCH * NIN / 2) / 256, 256>>>(X);

    // join: GEMM needs both preps
    cudaStreamWaitEvent(0, ev_join, 0);

    dim3 grid(BATCH / BM, NOUT / BN, SPLITK);   // (8, 4, 4) = 128 CTAs
    kan_gemm_kernel<<<grid, 256, SMEM_TOTAL>>>();

    reduce_kernel<<<(BATCH * NOUT / 4) / 256, 256>>>((float*)d_out);
}